// round 12
// baseline (speedup 1.0000x reference)
// ProtoPNet head — raw mma.sync.m16n8k16 fp16-split (3-term, fp32 acc),
// fully register-resident GEMM1->GEMM2->GEMM3 pipeline. One CTA per image.
#include <cuda_runtime.h>
#include <cuda_fp16.h>
#include <cstdint>

#define NB 256
#define CIN 256
#define HW 784
#define DD 64
#define PP 200
#define NCLS 10

constexpr int THREADS = 256;
constexpr int NW = 8;
constexpr int STILE = 128;
constexpr int KCH = 128;            // channels per staged X chunk
constexpr int NCHUNK = CIN / KCH;   // 2
constexpr int NTILES = 7;

constexpr int LDW1 = 264;   // W1 row pitch (halfs): 256+8
constexpr int LDW2 = 72;    // W2 row pitch: 64+8
constexpr int LDPT = 72;    // proto row pitch: 64+8
constexpr int LDX  = 136;   // X chunk row pitch: 128+8

// ---- smem byte offsets ----
constexpr int OFF_W1H = 0;                    // [64][264] half
constexpr int OFF_W1L = 33792;
constexpr int OFF_W2H = 67584;                // [64][72] half
constexpr int OFF_W2L = 76800;
constexpr int OFF_PH  = 86016;                // [200][72] half
constexpr int OFF_PL  = 114816;
constexpr int OFF_XH  = 143616;               // [128][136] half
constexpr int OFF_XL  = 178432;
constexpr int OFF_B1  = 213248;               // [64] f32
constexpr int OFF_B2  = 213504;
constexpr int OFF_P2  = 213760;               // [200] f32
constexpr int OFF_MIND = 214560;              // [200] i32
constexpr int SMEM_BYTES = 215360;            // ~210.3 KB

__device__ __forceinline__ void mma16816(float* c, const uint32_t* a,
                                         const uint32_t* b) {
    asm volatile(
        "mma.sync.aligned.m16n8k16.row.col.f32.f16.f16.f32 "
        "{%0,%1,%2,%3}, {%4,%5,%6,%7}, {%8,%9}, {%0,%1,%2,%3};"
        : "+f"(c[0]), "+f"(c[1]), "+f"(c[2]), "+f"(c[3])
        : "r"(a[0]), "r"(a[1]), "r"(a[2]), "r"(a[3]), "r"(b[0]), "r"(b[1]));
}

__device__ __forceinline__ void split_h2(float x, float y, uint32_t& hi, uint32_t& lo) {
    __half hx = __float2half_rn(x), hy = __float2half_rn(y);
    __half lx = __float2half_rn(x - __half2float(hx));
    __half ly = __float2half_rn(y - __half2float(hy));
    __half2 h = __halves2half2(hx, hy), l = __halves2half2(lx, ly);
    hi = *(uint32_t*)&h; lo = *(uint32_t*)&l;
}
__device__ __forceinline__ float sigm(float v) { return 1.f / (1.f + __expf(-v)); }

__global__ __launch_bounds__(THREADS, 1)
void proto_rmma_kernel(const float* __restrict__ x,
                       const float* __restrict__ W1,
                       const float* __restrict__ b1,
                       const float* __restrict__ W2,
                       const float* __restrict__ b2,
                       const float* __restrict__ proto,
                       const float* __restrict__ lastW,
                       const float* __restrict__ lastB,
                       float* __restrict__ out_logits,
                       float* __restrict__ out_mind)
{
    extern __shared__ char smem[];
    __half* sW1H = (__half*)(smem + OFF_W1H);
    __half* sW1L = (__half*)(smem + OFF_W1L);
    __half* sW2H = (__half*)(smem + OFF_W2H);
    __half* sW2L = (__half*)(smem + OFF_W2L);
    __half* sPH  = (__half*)(smem + OFF_PH);
    __half* sPL  = (__half*)(smem + OFF_PL);
    __half* sXH  = (__half*)(smem + OFF_XH);
    __half* sXL  = (__half*)(smem + OFF_XL);
    float*  sB1  = (float*)(smem + OFF_B1);
    float*  sB2  = (float*)(smem + OFF_B2);
    float*  sP2  = (float*)(smem + OFF_P2);
    int*    sMind = (int*)(smem + OFF_MIND);

    const int tid  = threadIdx.x;
    const int lane = tid & 31;
    const int warp = tid >> 5;        // 0..7, owns spatial rows [warp*16,+16)
    const int g    = lane >> 2;       // group 0..7 (row within fragment)
    const int tg   = lane & 3;        // thread-in-group
    const int wrow = warp * 16;
    const int n    = blockIdx.x;

    // ---- Prologue: weights hi/lo split into smem (row-major [n][k]) ----
    for (int i = tid; i < DD * CIN; i += THREADS) {      // W1[d][c]
        int d = i >> 8, c = i & 255;
        float v = W1[i];
        __half h = __float2half_rn(v);
        sW1H[d * LDW1 + c] = h;
        sW1L[d * LDW1 + c] = __float2half_rn(v - __half2float(h));
    }
    for (int i = tid; i < DD * DD; i += THREADS) {       // W2[d2][d1]
        int d2 = i >> 6, d1 = i & 63;
        float v = W2[i];
        __half h = __float2half_rn(v);
        sW2H[d2 * LDW2 + d1] = h;
        sW2L[d2 * LDW2 + d1] = __float2half_rn(v - __half2float(h));
    }
    for (int i = tid; i < PP * DD; i += THREADS) {       // proto[p][c]
        int p = i >> 6, c = i & 63;
        float v = proto[i];
        __half h = __float2half_rn(v);
        sPH[p * LDPT + c] = h;
        sPL[p * LDPT + c] = __float2half_rn(v - __half2float(h));
    }
    if (tid < DD) { sB1[tid] = b1[tid]; sB2[tid] = b2[tid]; }
    if (tid < PP) {
        float s = 0.f;
        #pragma unroll 8
        for (int c = 0; c < DD; c++) { float v = proto[tid * DD + c]; s += v * v; }
        sP2[tid] = s;
        sMind[tid] = 0x7F7FFFFF;
    }
    __syncthreads();

    const float* xg = x + (size_t)n * CIN * HW;

    for (int st = 0; st < NTILES; st++) {
        const int s0 = st * STILE;
        const int validCnt = HW - s0;

        // ===== GEMM1: C1[128,64] = X * W1^T, K=256 in 2 staged chunks =====
        float c1[8][4];
        #pragma unroll
        for (int i = 0; i < 8; i++)
            #pragma unroll
            for (int j = 0; j < 4; j++) c1[i][j] = 0.f;

        for (int ch = 0; ch < NCHUNK; ch++) {
            __syncthreads();    // X tiles free
            #pragma unroll 4
            for (int it = 0; it < (KCH * STILE) / THREADS; it++) {   // 64
                int idx = it * THREADS + tid;
                int s = idx & 127, c = idx >> 7;
                int gs = s0 + s;
                float v = (gs < HW) ? xg[(ch * KCH + c) * HW + gs] : 0.f;
                __half h = __float2half_rn(v);
                sXH[s * LDX + c] = h;
                sXL[s * LDX + c] = __float2half_rn(v - __half2float(h));
            }
            __syncthreads();
            #pragma unroll
            for (int ks = 0; ks < KCH / 16; ks++) {                  // 8
                const int k0 = ks * 16 + tg * 2;
                uint32_t ah[4], al[4];
                ah[0] = *(const uint32_t*)(sXH + (wrow + g) * LDX + k0);
                ah[1] = *(const uint32_t*)(sXH + (wrow + g + 8) * LDX + k0);
                ah[2] = *(const uint32_t*)(sXH + (wrow + g) * LDX + k0 + 8);
                ah[3] = *(const uint32_t*)(sXH + (wrow + g + 8) * LDX + k0 + 8);
                al[0] = *(const uint32_t*)(sXL + (wrow + g) * LDX + k0);
                al[1] = *(const uint32_t*)(sXL + (wrow + g + 8) * LDX + k0);
                al[2] = *(const uint32_t*)(sXL + (wrow + g) * LDX + k0 + 8);
                al[3] = *(const uint32_t*)(sXL + (wrow + g + 8) * LDX + k0 + 8);
                const int kw = ch * KCH + k0;
                #pragma unroll
                for (int nt = 0; nt < 8; nt++) {
                    const int nr = nt * 8 + g;
                    uint32_t bh[2], bl[2];
                    bh[0] = *(const uint32_t*)(sW1H + nr * LDW1 + kw);
                    bh[1] = *(const uint32_t*)(sW1H + nr * LDW1 + kw + 8);
                    bl[0] = *(const uint32_t*)(sW1L + nr * LDW1 + kw);
                    bl[1] = *(const uint32_t*)(sW1L + nr * LDW1 + kw + 8);
                    mma16816(c1[nt], ah, bh);
                    mma16816(c1[nt], al, bh);
                    mma16816(c1[nt], ah, bl);
                }
            }
        }

        // ---- Epilogue 1 (registers): h = relu(c1+b1) -> A fragments ----
        uint32_t a2h[4][4], a2l[4][4];
        #pragma unroll
        for (int kt = 0; kt < 4; kt++) {
            const float2 bA = *(const float2*)(sB1 + (2 * kt) * 8 + tg * 2);
            const float2 bB = *(const float2*)(sB1 + (2 * kt + 1) * 8 + tg * 2);
            split_h2(fmaxf(c1[2 * kt][0] + bA.x, 0.f),
                     fmaxf(c1[2 * kt][1] + bA.y, 0.f), a2h[kt][0], a2l[kt][0]);
            split_h2(fmaxf(c1[2 * kt][2] + bA.x, 0.f),
                     fmaxf(c1[2 * kt][3] + bA.y, 0.f), a2h[kt][1], a2l[kt][1]);
            split_h2(fmaxf(c1[2 * kt + 1][0] + bB.x, 0.f),
                     fmaxf(c1[2 * kt + 1][1] + bB.y, 0.f), a2h[kt][2], a2l[kt][2]);
            split_h2(fmaxf(c1[2 * kt + 1][2] + bB.x, 0.f),
                     fmaxf(c1[2 * kt + 1][3] + bB.y, 0.f), a2h[kt][3], a2l[kt][3]);
        }

        // ===== GEMM2: C2[128,64] = h * W2^T (K=64) =====
        float c2[8][4];
        #pragma unroll
        for (int i = 0; i < 8; i++)
            #pragma unroll
            for (int j = 0; j < 4; j++) c2[i][j] = 0.f;
        #pragma unroll
        for (int kt = 0; kt < 4; kt++) {
            const int kw = kt * 16 + tg * 2;
            #pragma unroll
            for (int nt = 0; nt < 8; nt++) {
                const int nr = nt * 8 + g;
                uint32_t bh[2], bl[2];
                bh[0] = *(const uint32_t*)(sW2H + nr * LDW2 + kw);
                bh[1] = *(const uint32_t*)(sW2H + nr * LDW2 + kw + 8);
                bl[0] = *(const uint32_t*)(sW2L + nr * LDW2 + kw);
                bl[1] = *(const uint32_t*)(sW2L + nr * LDW2 + kw + 8);
                mma16816(c2[nt], a2h[kt], bh);
                mma16816(c2[nt], a2l[kt], bh);
                mma16816(c2[nt], a2h[kt], bl);
            }
        }

        // ---- Epilogue 2 (registers): f = sigmoid(c2+b2); x2 via quad shuffles ----
        uint32_t a3h[4][4], a3l[4][4];
        float x2a = 0.f, x2b = 0.f;   // rows wrow+g, wrow+g+8
        #pragma unroll
        for (int kt = 0; kt < 4; kt++) {
            const float2 bA = *(const float2*)(sB2 + (2 * kt) * 8 + tg * 2);
            const float2 bB = *(const float2*)(sB2 + (2 * kt + 1) * 8 + tg * 2);
            float f00 = sigm(c2[2 * kt][0] + bA.x);
            float f01 = sigm(c2[2 * kt][1] + bA.y);
            float f02 = sigm(c2[2 * kt][2] + bA.x);
            float f03 = sigm(c2[2 * kt][3] + bA.y);
            float f10 = sigm(c2[2 * kt + 1][0] + bB.x);
            float f11 = sigm(c2[2 * kt + 1][1] + bB.y);
            float f12 = sigm(c2[2 * kt + 1][2] + bB.x);
            float f13 = sigm(c2[2 * kt + 1][3] + bB.y);
            x2a += f00 * f00 + f01 * f01 + f10 * f10 + f11 * f11;
            x2b += f02 * f02 + f03 * f03 + f12 * f12 + f13 * f13;
            split_h2(f00, f01, a3h[kt][0], a3l[kt][0]);
            split_h2(f02, f03, a3h[kt][1], a3l[kt][1]);
            split_h2(f10, f11, a3h[kt][2], a3l[kt][2]);
            split_h2(f12, f13, a3h[kt][3], a3l[kt][3]);
        }
        x2a += __shfl_xor_sync(0xffffffffu, x2a, 1);
        x2a += __shfl_xor_sync(0xffffffffu, x2a, 2);
        x2b += __shfl_xor_sync(0xffffffffu, x2b, 1);
        x2b += __shfl_xor_sync(0xffffffffu, x2b, 2);

        // ===== GEMM3 + distance/min epilogue, per 8-wide prototype tile =====
        const bool v0 = (wrow + g < validCnt);
        const bool v1 = (wrow + g + 8 < validCnt);
        for (int nt = 0; nt < PP / 8; nt++) {           // 25
            float c3[4] = {0.f, 0.f, 0.f, 0.f};
            #pragma unroll
            for (int kt = 0; kt < 4; kt++) {
                const int kw = kt * 16 + tg * 2;
                const int nr = nt * 8 + g;
                uint32_t bh[2], bl[2];
                bh[0] = *(const uint32_t*)(sPH + nr * LDPT + kw);
                bh[1] = *(const uint32_t*)(sPH + nr * LDPT + kw + 8);
                bl[0] = *(const uint32_t*)(sPL + nr * LDPT + kw);
                bl[1] = *(const uint32_t*)(sPL + nr * LDPT + kw + 8);
                mma16816(c3, a3h[kt], bh);
                mma16816(c3, a3l[kt], bh);
                mma16816(c3, a3h[kt], bl);
            }
            const int p0 = nt * 8 + tg * 2;
            const float2 pn = *(const float2*)(sP2 + p0);
            const float FMAX = 3.402823466e+38f;
            float d00 = v0 ? fmaxf(x2a - 2.f * c3[0] + pn.x, 0.f) : FMAX;
            float d01 = v0 ? fmaxf(x2a - 2.f * c3[1] + pn.y, 0.f) : FMAX;
            float d10 = v1 ? fmaxf(x2b - 2.f * c3[2] + pn.x, 0.f) : FMAX;
            float d11 = v1 ? fmaxf(x2b - 2.f * c3[3] + pn.y, 0.f) : FMAX;
            float m0 = fminf(d00, d10);
            float m1 = fminf(d01, d11);
            #pragma unroll
            for (int o = 4; o <= 16; o <<= 1) {
                m0 = fminf(m0, __shfl_xor_sync(0xffffffffu, m0, o));
                m1 = fminf(m1, __shfl_xor_sync(0xffffffffu, m1, o));
            }
            if (g == 0) {
                atomicMin(sMind + p0,     __float_as_int(m0));
                atomicMin(sMind + p0 + 1, __float_as_int(m1));
            }
        }
        // next tile's staging __syncthreads protects X reuse
    }
    __syncthreads();

    // ---- Outputs ----
    if (tid < PP)
        out_mind[n * PP + tid] = __int_as_float(sMind[tid]);
    for (int cls = warp; cls < NCLS; cls += NW) {   // warp per class, strided
        float ssum = 0.f;
        for (int p = lane; p < PP; p += 32)
            ssum += __int_as_float(sMind[p]) * lastW[cls * PP + p];
        #pragma unroll
        for (int o = 16; o > 0; o >>= 1)
            ssum += __shfl_xor_sync(0xffffffffu, ssum, o);
        if (lane == 0)
            out_logits[n * NCLS + cls] = lastB[cls] - ssum;   // act = -min_dist
    }
}

extern "C" void kernel_launch(void* const* d_in, const int* in_sizes, int n_in,
                              void* d_out, int out_size) {
    (void)in_sizes; (void)n_in; (void)out_size;
    const float* x     = (const float*)d_in[0];
    const float* W1    = (const float*)d_in[1];
    const float* b1    = (const float*)d_in[2];
    const float* W2    = (const float*)d_in[3];
    const float* b2    = (const float*)d_in[4];
    const float* proto = (const float*)d_in[5];
    const float* lastW = (const float*)d_in[6];
    const float* lastB = (const float*)d_in[7];
    float* out        = (float*)d_out;
    float* out_logits = out;                 // (256,10)
    float* out_mind   = out + NB * NCLS;     // (256,200)

    cudaFuncSetAttribute(proto_rmma_kernel,
                         cudaFuncAttributeMaxDynamicSharedMemorySize, SMEM_BYTES);
    proto_rmma_kernel<<<NB, THREADS, SMEM_BYTES>>>(
        x, W1, b1, W2, b2, proto, lastW, lastB, out_logits, out_mind);
}

// round 13
// speedup vs baseline: 1.4997x; 1.4997x over previous
// ProtoPNet head, fully fused, WMMA fp16x2 (split hi/lo, 3-term MMA, fp32 acc).
// 512 threads = 16 warps: row-block pairs split the N dimension. One CTA/image.
#include <cuda_runtime.h>
#include <cuda_fp16.h>
#include <mma.h>
#include <cstdint>
using namespace nvcuda;

#define NB 256
#define CIN 256
#define HW 784
#define DD 64
#define PP 200
#define NCLS 10

constexpr int THREADS = 512;
constexpr int NW = 16;
constexpr int STILE = 128;
constexpr int KCH = 64;             // channels per GEMM1 chunk
constexpr int NCHUNK = CIN / KCH;   // 4
constexpr int NTILES = 7;
constexpr int LDW = 72;             // W1T/W2T leading dim (halfs)
constexpr int LDA = 72;             // A (X/h/f) leading dim (halfs)
constexpr int LDP = 216;            // P^T leading dim (halfs)
constexpr int PPAD = 208;           // 13 x 16 n-tiles
constexpr int LDC = 20;             // CW staging leading dim (floats)

// ---- smem byte offsets ----
constexpr int OFF_W1H = 0;               // [256][72] half
constexpr int OFF_W1L = 36864;
constexpr int OFF_W2H = 73728;           // [64][72] half
constexpr int OFF_W2L = 82944;
constexpr int OFF_PTH = 92160;           // [64][216] half
constexpr int OFF_PTL = 119808;
constexpr int OFF_AH  = 147456;          // [128][72] half (X chunk / h / f)
constexpr int OFF_AL  = 165888;
constexpr int OFF_CW  = 184320;          // 16 x [16][20] float = 20480
constexpr int OFF_X2  = 204800;          // [128] float
constexpr int OFF_P2  = 205312;          // [208] float
constexpr int OFF_B1  = 206144;          // [64] float
constexpr int OFF_B2  = 206400;          // [64] float
constexpr int OFF_MIND = 206656;         // [208] int
constexpr int SMEM_BYTES = 207488;       // ~202.6 KB

using FragA = wmma::fragment<wmma::matrix_a, 16, 16, 16, __half, wmma::row_major>;
using FragB = wmma::fragment<wmma::matrix_b, 16, 16, 16, __half, wmma::row_major>;
using FragC = wmma::fragment<wmma::accumulator, 16, 16, 16, float>;

__device__ __forceinline__ void split2(float v, __half& hi, __half& lo) {
    hi = __float2half_rn(v);
    lo = __float2half_rn(v - __half2float(hi));
}

__global__ __launch_bounds__(THREADS, 1)
void proto_h2w16_kernel(const float* __restrict__ x,
                        const float* __restrict__ W1,
                        const float* __restrict__ b1,
                        const float* __restrict__ W2,
                        const float* __restrict__ b2,
                        const float* __restrict__ proto,
                        const float* __restrict__ lastW,
                        const float* __restrict__ lastB,
                        float* __restrict__ out_logits,
                        float* __restrict__ out_mind)
{
    extern __shared__ char smem[];
    __half* sW1H = (__half*)(smem + OFF_W1H);
    __half* sW1L = (__half*)(smem + OFF_W1L);
    __half* sW2H = (__half*)(smem + OFF_W2H);
    __half* sW2L = (__half*)(smem + OFF_W2L);
    __half* sPTH = (__half*)(smem + OFF_PTH);
    __half* sPTL = (__half*)(smem + OFF_PTL);
    __half* sAH  = (__half*)(smem + OFF_AH);
    __half* sAL  = (__half*)(smem + OFF_AL);
    float*  sCWb = (float*)(smem + OFF_CW);
    float*  sX2  = (float*)(smem + OFF_X2);
    float*  sP2  = (float*)(smem + OFF_P2);
    float*  sB1  = (float*)(smem + OFF_B1);
    float*  sB2  = (float*)(smem + OFF_B2);
    int*    sMind = (int*)(smem + OFF_MIND);

    const int tid  = threadIdx.x;
    const int lane = tid & 31;
    const int warp = tid >> 5;          // 0..15
    const int rw   = warp & 7;          // row block: rows [rw*16, +16)
    const int ch2  = warp >> 3;         // column half (0/1)
    const int wrow = rw * 16;
    const int n    = blockIdx.x;

    // ---- Prologue: weights transposed + hi/lo split into smem ----
    for (int i = tid; i < DD * CIN; i += THREADS) {      // W1[d][c] -> [c][d]
        int d = i >> 8, c = i & 255;
        __half hi, lo; split2(W1[i], hi, lo);
        sW1H[c * LDW + d] = hi; sW1L[c * LDW + d] = lo;
    }
    for (int i = tid; i < DD * DD; i += THREADS) {       // W2[d2][d1] -> [d1][d2]
        int d2 = i >> 6, d1 = i & 63;
        __half hi, lo; split2(W2[i], hi, lo);
        sW2H[d1 * LDW + d2] = hi; sW2L[d1 * LDW + d2] = lo;
    }
    for (int i = tid; i < PP * DD; i += THREADS) {       // proto[p][c] -> [c][p]
        int p = i >> 6, c = i & 63;
        __half hi, lo; split2(proto[i], hi, lo);
        sPTH[c * LDP + p] = hi; sPTL[c * LDP + p] = lo;
    }
    for (int i = tid; i < DD * (LDP - PP); i += THREADS) {  // zero pad cols
        int c = i / (LDP - PP), p = PP + i % (LDP - PP);
        sPTH[c * LDP + p] = __float2half(0.f);
        sPTL[c * LDP + p] = __float2half(0.f);
    }
    if (tid < DD) { sB1[tid] = b1[tid]; sB2[tid] = b2[tid]; }
    if (tid < PPAD) {
        float s = 0.f;
        if (tid < PP) {
            #pragma unroll 8
            for (int c = 0; c < DD; c++) { float v = proto[tid * DD + c]; s += v * v; }
        }
        sP2[tid] = s;
        sMind[tid] = 0x7F7FFFFF;
    }
    __syncthreads();

    const float* xg = x + (size_t)n * CIN * HW;
    float* cw = sCWb + warp * (16 * LDC);
    const int col = lane & 15;
    const int r0  = (lane >> 4) * 8;

    for (int st = 0; st < NTILES; st++) {
        const int s0 = st * STILE;
        const int validCnt = HW - s0;

        // ===== GEMM1: C1[128,64] = X * W1T; warp does 2 of 4 n-tiles =====
        FragC c1[2];
        wmma::fill_fragment(c1[0], 0.f);
        wmma::fill_fragment(c1[1], 0.f);

        for (int ch = 0; ch < NCHUNK; ch++) {
            __syncthreads();    // A tiles free (prev readers done)
            const int kbase = ch * KCH;
            #pragma unroll
            for (int it = 0; it < (KCH * STILE) / THREADS; it++) {  // 16
                int idx = it * THREADS + tid;
                int c = idx >> 7, s = idx & 127;
                int gs = s0 + s;
                float v = (gs < HW) ? xg[(kbase + c) * HW + gs] : 0.f;
                __half hi, lo; split2(v, hi, lo);
                sAH[s * LDA + c] = hi; sAL[s * LDA + c] = lo;
            }
            __syncthreads();
            #pragma unroll
            for (int ks = 0; ks < 4; ks++) {
                FragA ah, al;
                wmma::load_matrix_sync(ah, sAH + wrow * LDA + ks * 16, LDA);
                wmma::load_matrix_sync(al, sAL + wrow * LDA + ks * 16, LDA);
                const int kr = kbase + ks * 16;
                #pragma unroll
                for (int j = 0; j < 2; j++) {
                    const int nt = ch2 * 2 + j;
                    FragB bh, bl;
                    wmma::load_matrix_sync(bh, sW1H + kr * LDW + nt * 16, LDW);
                    wmma::mma_sync(c1[j], ah, bh, c1[j]);
                    wmma::mma_sync(c1[j], al, bh, c1[j]);
                    wmma::load_matrix_sync(bl, sW1L + kr * LDW + nt * 16, LDW);
                    wmma::mma_sync(c1[j], ah, bl, c1[j]);
                }
            }
        }
        __syncthreads();   // all warps done reading X before h overwrites A
        // epilogue 1: h = relu(v+b1) -> hi/lo into A tiles (rows wrow, 32 cols)
        #pragma unroll
        for (int j = 0; j < 2; j++) {
            wmma::store_matrix_sync(cw, c1[j], LDC, wmma::mem_row_major);
            __syncwarp();
            const int d = (ch2 * 2 + j) * 16 + col;
            #pragma unroll
            for (int jr = 0; jr < 8; jr++) {
                const int r = r0 + jr;
                float v = fmaxf(cw[r * LDC + col] + sB1[d], 0.f);
                __half hi, lo; split2(v, hi, lo);
                sAH[(wrow + r) * LDA + d] = hi;
                sAL[(wrow + r) * LDA + d] = lo;
            }
            __syncwarp();
        }
        __syncthreads();

        // ===== GEMM2: C2 = h * W2T (K=64); warp does 2 n-tiles =====
        FragC c2[2];
        wmma::fill_fragment(c2[0], 0.f);
        wmma::fill_fragment(c2[1], 0.f);
        #pragma unroll
        for (int ks = 0; ks < 4; ks++) {
            FragA ah, al;
            wmma::load_matrix_sync(ah, sAH + wrow * LDA + ks * 16, LDA);
            wmma::load_matrix_sync(al, sAL + wrow * LDA + ks * 16, LDA);
            #pragma unroll
            for (int j = 0; j < 2; j++) {
                const int nt = ch2 * 2 + j;
                FragB bh, bl;
                wmma::load_matrix_sync(bh, sW2H + (ks * 16) * LDW + nt * 16, LDW);
                wmma::mma_sync(c2[j], ah, bh, c2[j]);
                wmma::mma_sync(c2[j], al, bh, c2[j]);
                wmma::load_matrix_sync(bl, sW2L + (ks * 16) * LDW + nt * 16, LDW);
                wmma::mma_sync(c2[j], ah, bl, c2[j]);
            }
        }
        __syncthreads();   // all warps done reading h before f overwrites A
        // epilogue 2: f = sigmoid(v+b2) -> hi/lo into A tiles
        #pragma unroll
        for (int j = 0; j < 2; j++) {
            wmma::store_matrix_sync(cw, c2[j], LDC, wmma::mem_row_major);
            __syncwarp();
            const int d = (ch2 * 2 + j) * 16 + col;
            #pragma unroll
            for (int jr = 0; jr < 8; jr++) {
                const int r = r0 + jr;
                float v = cw[r * LDC + col] + sB2[d];
                float f = 1.f / (1.f + __expf(-v));
                __half hi, lo; split2(f, hi, lo);
                sAH[(wrow + r) * LDA + d] = hi;
                sAL[(wrow + r) * LDA + d] = lo;
            }
            __syncwarp();
        }
        __syncthreads();

        // ---- x2[r] = sum_d f_eff^2 (512 threads: 4 lanes per row) ----
        {
            const int r = tid >> 2, co = (tid & 3) * 16;
            float s2 = 0.f;
            #pragma unroll
            for (int j = 0; j < 16; j++) {
                float f = __half2float(sAH[r * LDA + co + j]) +
                          __half2float(sAL[r * LDA + co + j]);
                s2 += f * f;
            }
            s2 += __shfl_xor_sync(0xffffffffu, s2, 1);
            s2 += __shfl_xor_sync(0xffffffffu, s2, 2);
            if ((tid & 3) == 0) sX2[r] = s2;
        }
        __syncthreads();

        // ===== GEMM3: C3 = f * PT (K=64); warp-pair splits 13 tiles 7/6 =====
        {
            const int ntLo = (ch2 == 0) ? 0 : 7;
            const int ntHi = (ch2 == 0) ? 7 : 13;
            for (int nt = ntLo; nt < ntHi; nt++) {
                FragC c3;
                wmma::fill_fragment(c3, 0.f);
                #pragma unroll
                for (int ks = 0; ks < 4; ks++) {
                    FragA ah, al;
                    wmma::load_matrix_sync(ah, sAH + wrow * LDA + ks * 16, LDA);
                    wmma::load_matrix_sync(al, sAL + wrow * LDA + ks * 16, LDA);
                    FragB bh, bl;
                    wmma::load_matrix_sync(bh, sPTH + (ks * 16) * LDP + nt * 16, LDP);
                    wmma::mma_sync(c3, ah, bh, c3);
                    wmma::mma_sync(c3, al, bh, c3);
                    wmma::load_matrix_sync(bl, sPTL + (ks * 16) * LDP + nt * 16, LDP);
                    wmma::mma_sync(c3, ah, bl, c3);
                }
                wmma::store_matrix_sync(cw, c3, LDC, wmma::mem_row_major);
                __syncwarp();
                const int p = nt * 16 + col;
                const float pn2 = sP2[p];
                float mn = 3.402823466e+38f;
                #pragma unroll
                for (int jr = 0; jr < 8; jr++) {
                    const int r = r0 + jr;
                    if (wrow + r < validCnt) {
                        float v = cw[r * LDC + col];
                        mn = fminf(mn, fmaxf(sX2[wrow + r] - 2.f * v + pn2, 0.f));
                    }
                }
                mn = fminf(mn, __shfl_xor_sync(0xffffffffu, mn, 16));
                if (lane < 16 && p < PP)
                    atomicMin(sMind + p, __float_as_int(mn));
                __syncwarp();
            }
        }
        // next tile's chunk-staging __syncthreads protects A-tile reuse
    }
    __syncthreads();

    // ---- Outputs ----
    if (tid < PP)
        out_mind[n * PP + tid] = __int_as_float(sMind[tid]);
    for (int cls = warp; cls < NCLS; cls += NW) {   // warp per class
        float ssum = 0.f;
        for (int p = lane; p < PP; p += 32)
            ssum += __int_as_float(sMind[p]) * lastW[cls * PP + p];
        #pragma unroll
        for (int o = 16; o > 0; o >>= 1)
            ssum += __shfl_xor_sync(0xffffffffu, ssum, o);
        if (lane == 0)
            out_logits[n * NCLS + cls] = lastB[cls] - ssum;   // act = -min_dist
    }
}

extern "C" void kernel_launch(void* const* d_in, const int* in_sizes, int n_in,
                              void* d_out, int out_size) {
    (void)in_sizes; (void)n_in; (void)out_size;
    const float* x     = (const float*)d_in[0];
    const float* W1    = (const float*)d_in[1];
    const float* b1    = (const float*)d_in[2];
    const float* W2    = (const float*)d_in[3];
    const float* b2    = (const float*)d_in[4];
    const float* proto = (const float*)d_in[5];
    const float* lastW = (const float*)d_in[6];
    const float* lastB = (const float*)d_in[7];
    float* out        = (float*)d_out;
    float* out_logits = out;                 // (256,10)
    float* out_mind   = out + NB * NCLS;     // (256,200)

    cudaFuncSetAttribute(proto_h2w16_kernel,
                         cudaFuncAttributeMaxDynamicSharedMemorySize, SMEM_BYTES);
    proto_h2w16_kernel<<<NB, THREADS, SMEM_BYTES>>>(
        x, W1, b1, W2, b2, proto, lastW, lastB, out_logits, out_mind);
}

// round 14
// speedup vs baseline: 1.5646x; 1.0433x over previous
// ProtoPNet head, fully fused, WMMA fp16x2 (split hi/lo, 3-term MMA, fp32 acc).
// 512 threads = 16 warps (row-block x N-half). Pipelined: GEMM1 LDG prefetch,
// GEMM3 register-resident A + overlapped next-tile X staging, fused ||f||^2.
#include <cuda_runtime.h>
#include <cuda_fp16.h>
#include <mma.h>
#include <cstdint>
using namespace nvcuda;

#define NB 256
#define CIN 256
#define HW 784
#define DD 64
#define PP 200
#define NCLS 10

constexpr int THREADS = 512;
constexpr int NW = 16;
constexpr int STILE = 128;
constexpr int KCH = 64;             // channels per GEMM1 chunk
constexpr int NCHUNK = CIN / KCH;   // 4
constexpr int NTILES = 7;
constexpr int LDW = 72;             // W1T/W2T leading dim (halfs)
constexpr int LDA = 72;             // A (X/h/f) leading dim (halfs)
constexpr int LDP = 216;            // P^T leading dim (halfs)
constexpr int PPAD = 208;           // 13 x 16 n-tiles
constexpr int LDC = 20;             // CW staging leading dim (floats)

// ---- smem byte offsets ----
constexpr int OFF_W1H = 0;               // [256][72] half
constexpr int OFF_W1L = 36864;
constexpr int OFF_W2H = 73728;           // [64][72] half
constexpr int OFF_W2L = 82944;
constexpr int OFF_PTH = 92160;           // [64][216] half
constexpr int OFF_PTL = 119808;
constexpr int OFF_AH  = 147456;          // [128][72] half (X chunk / h / f)
constexpr int OFF_AL  = 165888;
constexpr int OFF_CW  = 184320;          // 16 x [16][20] float = 20480
constexpr int OFF_X2  = 204800;          // [128] float
constexpr int OFF_P2  = 205312;          // [208] float
constexpr int OFF_B1  = 206144;          // [64] float
constexpr int OFF_B2  = 206400;          // [64] float
constexpr int OFF_MIND = 206656;         // [208] int
constexpr int SMEM_BYTES = 207488;       // ~202.6 KB

using FragA = wmma::fragment<wmma::matrix_a, 16, 16, 16, __half, wmma::row_major>;
using FragB = wmma::fragment<wmma::matrix_b, 16, 16, 16, __half, wmma::row_major>;
using FragC = wmma::fragment<wmma::accumulator, 16, 16, 16, float>;

__device__ __forceinline__ void split2(float v, __half& hi, __half& lo) {
    hi = __float2half_rn(v);
    lo = __float2half_rn(v - __half2float(hi));
}

__global__ __launch_bounds__(THREADS, 1)
void proto_h2p_kernel(const float* __restrict__ x,
                      const float* __restrict__ W1,
                      const float* __restrict__ b1,
                      const float* __restrict__ W2,
                      const float* __restrict__ b2,
                      const float* __restrict__ proto,
                      const float* __restrict__ lastW,
                      const float* __restrict__ lastB,
                      float* __restrict__ out_logits,
                      float* __restrict__ out_mind)
{
    extern __shared__ char smem[];
    __half* sW1H = (__half*)(smem + OFF_W1H);
    __half* sW1L = (__half*)(smem + OFF_W1L);
    __half* sW2H = (__half*)(smem + OFF_W2H);
    __half* sW2L = (__half*)(smem + OFF_W2L);
    __half* sPTH = (__half*)(smem + OFF_PTH);
    __half* sPTL = (__half*)(smem + OFF_PTL);
    __half* sAH  = (__half*)(smem + OFF_AH);
    __half* sAL  = (__half*)(smem + OFF_AL);
    float*  sCWb = (float*)(smem + OFF_CW);
    float*  sX2  = (float*)(smem + OFF_X2);
    float*  sP2  = (float*)(smem + OFF_P2);
    float*  sB1  = (float*)(smem + OFF_B1);
    float*  sB2  = (float*)(smem + OFF_B2);
    int*    sMind = (int*)(smem + OFF_MIND);

    const int tid  = threadIdx.x;
    const int lane = tid & 31;
    const int warp = tid >> 5;          // 0..15
    const int rw   = warp & 7;          // row block: rows [rw*16, +16)
    const int ch2  = warp >> 3;         // column half (0/1)
    const int wrow = rw * 16;
    const int n    = blockIdx.x;

    // ---- Prologue: weights transposed + hi/lo split into smem ----
    for (int i = tid; i < DD * CIN; i += THREADS) {      // W1[d][c] -> [c][d]
        int d = i >> 8, c = i & 255;
        __half hi, lo; split2(W1[i], hi, lo);
        sW1H[c * LDW + d] = hi; sW1L[c * LDW + d] = lo;
    }
    for (int i = tid; i < DD * DD; i += THREADS) {       // W2[d2][d1] -> [d1][d2]
        int d2 = i >> 6, d1 = i & 63;
        __half hi, lo; split2(W2[i], hi, lo);
        sW2H[d1 * LDW + d2] = hi; sW2L[d1 * LDW + d2] = lo;
    }
    for (int i = tid; i < PP * DD; i += THREADS) {       // proto[p][c] -> [c][p]
        int p = i >> 6, c = i & 63;
        __half hi, lo; split2(proto[i], hi, lo);
        sPTH[c * LDP + p] = hi; sPTL[c * LDP + p] = lo;
    }
    for (int i = tid; i < DD * (LDP - PP); i += THREADS) {  // zero pad cols
        int c = i / (LDP - PP), p = PP + i % (LDP - PP);
        sPTH[c * LDP + p] = __float2half(0.f);
        sPTL[c * LDP + p] = __float2half(0.f);
    }
    if (tid < DD) { sB1[tid] = b1[tid]; sB2[tid] = b2[tid]; }
    if (tid < PPAD) {
        float s = 0.f;
        if (tid < PP) {
            #pragma unroll 8
            for (int c = 0; c < DD; c++) { float v = proto[tid * DD + c]; s += v * v; }
        }
        sP2[tid] = s;
        sMind[tid] = 0x7F7FFFFF;
    }
    __syncthreads();

    const float* xg = x + (size_t)n * CIN * HW;
    float* cw = sCWb + warp * (16 * LDC);
    const int col = lane & 15;
    const int r0  = (lane >> 4) * 8;
    const int stg_c = tid >> 7;          // staging: base channel (x4 per thread? no: idx mapping below)

    // ---- stage tile 0, chunk 0 (channels 0..63) ----
    #pragma unroll
    for (int it = 0; it < 16; it++) {
        int idx = it * THREADS + tid;
        int c = idx >> 7, s = idx & 127;
        float v = xg[c * HW + s];        // tile 0: gs = s < 784 always
        __half hi, lo; split2(v, hi, lo);
        sAH[s * LDA + c] = hi; sAL[s * LDA + c] = lo;
    }
    __syncthreads();

    for (int st = 0; st < NTILES; st++) {
        const int s0 = st * STILE;
        const int validCnt = HW - s0;

        // ===== GEMM1: C1[128,64] = X * W1T; prefetch next chunk during MMA =====
        FragC c1[2];
        wmma::fill_fragment(c1[0], 0.f);
        wmma::fill_fragment(c1[1], 0.f);
        float pf[16];

        for (int ch = 0; ch < NCHUNK; ch++) {
            const int kbase = ch * KCH;
            if (ch + 1 < NCHUNK) {       // issue next chunk's LDGs first
                const int kn = (ch + 1) * KCH;
                #pragma unroll
                for (int it = 0; it < 16; it++) {
                    int idx = it * THREADS + tid;
                    int c = idx >> 7, s = idx & 127;
                    int gs = s0 + s;
                    pf[it] = (gs < HW) ? xg[(kn + c) * HW + gs] : 0.f;
                }
            }
            #pragma unroll
            for (int ks = 0; ks < 4; ks++) {
                FragA ah, al;
                wmma::load_matrix_sync(ah, sAH + wrow * LDA + ks * 16, LDA);
                wmma::load_matrix_sync(al, sAL + wrow * LDA + ks * 16, LDA);
                const int kr = kbase + ks * 16;
                #pragma unroll
                for (int j = 0; j < 2; j++) {
                    const int nt = ch2 * 2 + j;
                    FragB bh, bl;
                    wmma::load_matrix_sync(bh, sW1H + kr * LDW + nt * 16, LDW);
                    wmma::mma_sync(c1[j], ah, bh, c1[j]);
                    wmma::mma_sync(c1[j], al, bh, c1[j]);
                    wmma::load_matrix_sync(bl, sW1L + kr * LDW + nt * 16, LDW);
                    wmma::mma_sync(c1[j], ah, bl, c1[j]);
                }
            }
            if (ch + 1 < NCHUNK) {
                __syncthreads();         // all MMA reads of current chunk done
                #pragma unroll
                for (int it = 0; it < 16; it++) {
                    int idx = it * THREADS + tid;
                    int c = idx >> 7, s = idx & 127;
                    __half hi, lo; split2(pf[it], hi, lo);
                    sAH[s * LDA + c] = hi; sAL[s * LDA + c] = lo;
                }
                __syncthreads();
            }
        }
        __syncthreads();   // last chunk's reads done before h overwrites A
        // epilogue 1: h = relu(v+b1) -> hi/lo into A tiles; zero x2 accumulators
        if (tid < STILE) sX2[tid] = 0.f;
        #pragma unroll
        for (int j = 0; j < 2; j++) {
            wmma::store_matrix_sync(cw, c1[j], LDC, wmma::mem_row_major);
            __syncwarp();
            const int d = (ch2 * 2 + j) * 16 + col;
            #pragma unroll
            for (int jr = 0; jr < 8; jr++) {
                const int r = r0 + jr;
                float v = fmaxf(cw[r * LDC + col] + sB1[d], 0.f);
                __half hi, lo; split2(v, hi, lo);
                sAH[(wrow + r) * LDA + d] = hi;
                sAL[(wrow + r) * LDA + d] = lo;
            }
            __syncwarp();
        }
        __syncthreads();

        // ===== GEMM2: C2 = h * W2T (K=64); warp does 2 n-tiles =====
        FragC c2[2];
        wmma::fill_fragment(c2[0], 0.f);
        wmma::fill_fragment(c2[1], 0.f);
        #pragma unroll
        for (int ks = 0; ks < 4; ks++) {
            FragA ah, al;
            wmma::load_matrix_sync(ah, sAH + wrow * LDA + ks * 16, LDA);
            wmma::load_matrix_sync(al, sAL + wrow * LDA + ks * 16, LDA);
            #pragma unroll
            for (int j = 0; j < 2; j++) {
                const int nt = ch2 * 2 + j;
                FragB bh, bl;
                wmma::load_matrix_sync(bh, sW2H + (ks * 16) * LDW + nt * 16, LDW);
                wmma::mma_sync(c2[j], ah, bh, c2[j]);
                wmma::mma_sync(c2[j], al, bh, c2[j]);
                wmma::load_matrix_sync(bl, sW2L + (ks * 16) * LDW + nt * 16, LDW);
                wmma::mma_sync(c2[j], ah, bl, c2[j]);
            }
        }
        __syncthreads();   // all warps done reading h before f overwrites A
        // epilogue 2: f = sigmoid(v+b2) -> A tiles; fused ||f||^2 partials
        {
            float s2r[8] = {0.f, 0.f, 0.f, 0.f, 0.f, 0.f, 0.f, 0.f};
            #pragma unroll
            for (int j = 0; j < 2; j++) {
                wmma::store_matrix_sync(cw, c2[j], LDC, wmma::mem_row_major);
                __syncwarp();
                const int d = (ch2 * 2 + j) * 16 + col;
                #pragma unroll
                for (int jr = 0; jr < 8; jr++) {
                    const int r = r0 + jr;
                    float v = cw[r * LDC + col] + sB2[d];
                    float f = 1.f / (1.f + __expf(-v));
                    s2r[jr] += f * f;
                    __half hi, lo; split2(f, hi, lo);
                    sAH[(wrow + r) * LDA + d] = hi;
                    sAL[(wrow + r) * LDA + d] = lo;
                }
                __syncwarp();
            }
            #pragma unroll
            for (int jr = 0; jr < 8; jr++) {
                s2r[jr] += __shfl_xor_sync(0xffffffffu, s2r[jr], 1);
                s2r[jr] += __shfl_xor_sync(0xffffffffu, s2r[jr], 2);
                s2r[jr] += __shfl_xor_sync(0xffffffffu, s2r[jr], 4);
                s2r[jr] += __shfl_xor_sync(0xffffffffu, s2r[jr], 8);
            }
            if ((lane & 15) == 0) {
                #pragma unroll
                for (int jr = 0; jr < 8; jr++)
                    atomicAdd(sX2 + wrow + r0 + jr, s2r[jr]);
            }
        }
        __syncthreads();

        // ---- hoist GEMM3 A fragments, then overlap next-tile X staging ----
        FragA a3h[4], a3l[4];
        #pragma unroll
        for (int ks = 0; ks < 4; ks++) {
            wmma::load_matrix_sync(a3h[ks], sAH + wrow * LDA + ks * 16, LDA);
            wmma::load_matrix_sync(a3l[ks], sAL + wrow * LDA + ks * 16, LDA);
        }
        __syncthreads();   // all hoists done before staging overwrites A
        if (st + 1 < NTILES) {
            const int ns0 = (st + 1) * STILE;
            #pragma unroll
            for (int it = 0; it < 16; it++) {
                int idx = it * THREADS + tid;
                int c = idx >> 7, s = idx & 127;
                int gs = ns0 + s;
                float v = (gs < HW) ? xg[c * HW + gs] : 0.f;
                __half hi, lo; split2(v, hi, lo);
                sAH[s * LDA + c] = hi; sAL[s * LDA + c] = lo;
            }
        }
        __syncthreads();   // staged chunk visible for next tile's GEMM1

        // ===== GEMM3: C3 = f * PT (K=64); register A; warp-pair splits 7/6 =====
        {
            const int ntLo = (ch2 == 0) ? 0 : 7;
            const int ntHi = (ch2 == 0) ? 7 : 13;
            for (int nt = ntLo; nt < ntHi; nt++) {
                FragC c3;
                wmma::fill_fragment(c3, 0.f);
                #pragma unroll
                for (int ks = 0; ks < 4; ks++) {
                    FragB bh, bl;
                    wmma::load_matrix_sync(bh, sPTH + (ks * 16) * LDP + nt * 16, LDP);
                    wmma::mma_sync(c3, a3h[ks], bh, c3);
                    wmma::mma_sync(c3, a3l[ks], bh, c3);
                    wmma::load_matrix_sync(bl, sPTL + (ks * 16) * LDP + nt * 16, LDP);
                    wmma::mma_sync(c3, a3h[ks], bl, c3);
                }
                wmma::store_matrix_sync(cw, c3, LDC, wmma::mem_row_major);
                __syncwarp();
                const int p = nt * 16 + col;
                const float pn2 = sP2[p];
                float mn = 3.402823466e+38f;
                #pragma unroll
                for (int jr = 0; jr < 8; jr++) {
                    const int r = r0 + jr;
                    if (wrow + r < validCnt) {
                        float v = cw[r * LDC + col];
                        mn = fminf(mn, fmaxf(sX2[wrow + r] - 2.f * v + pn2, 0.f));
                    }
                }
                mn = fminf(mn, __shfl_xor_sync(0xffffffffu, mn, 16));
                if (lane < 16 && p < PP)
                    atomicMin(sMind + p, __float_as_int(mn));
                __syncwarp();
            }
        }
        // no tile-end barrier needed: next GEMM1 reads the already-synced staged
        // chunk; sMind consumers sync below after the loop
    }
    __syncthreads();

    // ---- Outputs ----
    if (tid < PP)
        out_mind[n * PP + tid] = __int_as_float(sMind[tid]);
    for (int cls = warp; cls < NCLS; cls += NW) {   // warp per class
        float ssum = 0.f;
        for (int p = lane; p < PP; p += 32)
            ssum += __int_as_float(sMind[p]) * lastW[cls * PP + p];
        #pragma unroll
        for (int o = 16; o > 0; o >>= 1)
            ssum += __shfl_xor_sync(0xffffffffu, ssum, o);
        if (lane == 0)
            out_logits[n * NCLS + cls] = lastB[cls] - ssum;   // act = -min_dist
    }
}

extern "C" void kernel_launch(void* const* d_in, const int* in_sizes, int n_in,
                              void* d_out, int out_size) {
    (void)in_sizes; (void)n_in; (void)out_size;
    const float* x     = (const float*)d_in[0];
    const float* W1    = (const float*)d_in[1];
    const float* b1    = (const float*)d_in[2];
    const float* W2    = (const float*)d_in[3];
    const float* b2    = (const float*)d_in[4];
    const float* proto = (const float*)d_in[5];
    const float* lastW = (const float*)d_in[6];
    const float* lastB = (const float*)d_in[7];
    float* out        = (float*)d_out;
    float* out_logits = out;                 // (256,10)
    float* out_mind   = out + NB * NCLS;     // (256,200)

    cudaFuncSetAttribute(proto_h2p_kernel,
                         cudaFuncAttributeMaxDynamicSharedMemorySize, SMEM_BYTES);
    proto_h2p_kernel<<<NB, THREADS, SMEM_BYTES>>>(
        x, W1, b1, W2, b2, proto, lastW, lastB, out_logits, out_mind);
}

// round 16
// speedup vs baseline: 1.8183x; 1.1621x over previous
// ProtoPNet head, fully fused, WMMA fp16x2 (split hi/lo, 3-term MMA, fp32 acc).
// 512 threads = 16 warps (row-block x N-half). X staged COL-MAJOR (conflict-free
// STS) + col_major A fragments in GEMM1; pipelined LDG prefetch; GEMM3 register
// A + overlapped next-tile staging; fused ||f||^2.
#include <cuda_runtime.h>
#include <cuda_fp16.h>
#include <mma.h>
#include <cstdint>
using namespace nvcuda;

#define NB 256
#define CIN 256
#define HW 784
#define DD 64
#define PP 200
#define NCLS 10

constexpr int THREADS = 512;
constexpr int NW = 16;
constexpr int STILE = 128;
constexpr int KCH = 64;             // channels per GEMM1 chunk
constexpr int NCHUNK = CIN / KCH;   // 4
constexpr int NTILES = 7;
constexpr int LDW = 72;             // W1T/W2T leading dim (halfs)
constexpr int LDA = 72;             // h/f tile leading dim (halfs, row-major)
constexpr int LDXC = 136;           // X chunk leading dim (halfs, col-major [c][s])
constexpr int LDP = 216;            // P^T leading dim (halfs)
constexpr int PPAD = 208;           // 13 x 16 n-tiles
constexpr int LDC = 20;             // CW staging leading dim (floats)

// ---- smem byte offsets ----
constexpr int OFF_W1H = 0;               // [256][72] half
constexpr int OFF_W1L = 36864;
constexpr int OFF_W2H = 73728;           // [64][72] half
constexpr int OFF_W2L = 82944;
constexpr int OFF_PTH = 92160;           // [64][216] half
constexpr int OFF_PTL = 119808;
constexpr int OFF_AH  = 147456;          // X chunk [64][136] cm / h,f [128][72] rm
constexpr int OFF_AL  = 165888;
constexpr int OFF_CW  = 184320;          // 16 x [16][20] float = 20480
constexpr int OFF_X2  = 204800;          // [128] float
constexpr int OFF_P2  = 205312;          // [208] float
constexpr int OFF_B1  = 206144;          // [64] float
constexpr int OFF_B2  = 206400;          // [64] float
constexpr int OFF_MIND = 206656;         // [208] int
constexpr int SMEM_BYTES = 207488;       // ~202.6 KB

using FragA  = wmma::fragment<wmma::matrix_a, 16, 16, 16, __half, wmma::row_major>;
using FragAc = wmma::fragment<wmma::matrix_a, 16, 16, 16, __half, wmma::col_major>;
using FragB  = wmma::fragment<wmma::matrix_b, 16, 16, 16, __half, wmma::row_major>;
using FragC  = wmma::fragment<wmma::accumulator, 16, 16, 16, float>;

__device__ __forceinline__ void split2(float v, __half& hi, __half& lo) {
    hi = __float2half_rn(v);
    lo = __float2half_rn(v - __half2float(hi));
}

__global__ __launch_bounds__(THREADS, 1)
void proto_h2c_kernel(const float* __restrict__ x,
                      const float* __restrict__ W1,
                      const float* __restrict__ b1,
                      const float* __restrict__ W2,
                      const float* __restrict__ b2,
                      const float* __restrict__ proto,
                      const float* __restrict__ lastW,
                      const float* __restrict__ lastB,
                      float* __restrict__ out_logits,
                      float* __restrict__ out_mind)
{
    extern __shared__ char smem[];
    __half* sW1H = (__half*)(smem + OFF_W1H);
    __half* sW1L = (__half*)(smem + OFF_W1L);
    __half* sW2H = (__half*)(smem + OFF_W2H);
    __half* sW2L = (__half*)(smem + OFF_W2L);
    __half* sPTH = (__half*)(smem + OFF_PTH);
    __half* sPTL = (__half*)(smem + OFF_PTL);
    __half* sAH  = (__half*)(smem + OFF_AH);
    __half* sAL  = (__half*)(smem + OFF_AL);
    float*  sCWb = (float*)(smem + OFF_CW);
    float*  sX2  = (float*)(smem + OFF_X2);
    float*  sP2  = (float*)(smem + OFF_P2);
    float*  sB1  = (float*)(smem + OFF_B1);
    float*  sB2  = (float*)(smem + OFF_B2);
    int*    sMind = (int*)(smem + OFF_MIND);

    const int tid  = threadIdx.x;
    const int lane = tid & 31;
    const int warp = tid >> 5;          // 0..15
    const int rw   = warp & 7;          // row block: rows [rw*16, +16)
    const int ch2  = warp >> 3;         // column half (0/1)
    const int wrow = rw * 16;
    const int n    = blockIdx.x;

    // ---- Prologue: weights transposed + hi/lo split into smem ----
    for (int i = tid; i < DD * CIN; i += THREADS) {      // W1[d][c] -> [c][d]
        int d = i >> 8, c = i & 255;
        __half hi, lo; split2(W1[i], hi, lo);
        sW1H[c * LDW + d] = hi; sW1L[c * LDW + d] = lo;
    }
    for (int i = tid; i < DD * DD; i += THREADS) {       // W2[d2][d1] -> [d1][d2]
        int d2 = i >> 6, d1 = i & 63;
        __half hi, lo; split2(W2[i], hi, lo);
        sW2H[d1 * LDW + d2] = hi; sW2L[d1 * LDW + d2] = lo;
    }
    for (int i = tid; i < PP * DD; i += THREADS) {       // proto[p][c] -> [c][p]
        int p = i >> 6, c = i & 63;
        __half hi, lo; split2(proto[i], hi, lo);
        sPTH[c * LDP + p] = hi; sPTL[c * LDP + p] = lo;
    }
    for (int i = tid; i < DD * (LDP - PP); i += THREADS) {  // zero pad cols
        int c = i / (LDP - PP), p = PP + i % (LDP - PP);
        sPTH[c * LDP + p] = __float2half(0.f);
        sPTL[c * LDP + p] = __float2half(0.f);
    }
    if (tid < DD) { sB1[tid] = b1[tid]; sB2[tid] = b2[tid]; }
    if (tid < PPAD) {
        float s = 0.f;
        if (tid < PP) {
            #pragma unroll 8
            for (int c = 0; c < DD; c++) { float v = proto[tid * DD + c]; s += v * v; }
        }
        sP2[tid] = s;
        sMind[tid] = 0x7F7FFFFF;
    }
    __syncthreads();

    const float* xg = x + (size_t)n * CIN * HW;
    float* cw = sCWb + warp * (16 * LDC);
    const int col = lane & 15;
    const int r0  = (lane >> 4) * 8;

    // ---- stage tile 0, chunk 0 (channels 0..63), col-major [c][s] ----
    #pragma unroll
    for (int it = 0; it < 16; it++) {
        int idx = it * THREADS + tid;
        int c = idx >> 7, s = idx & 127;
        float v = xg[c * HW + s];        // tile 0: s < 784 always
        __half hi, lo; split2(v, hi, lo);
        sAH[c * LDXC + s] = hi; sAL[c * LDXC + s] = lo;
    }
    __syncthreads();

    for (int st = 0; st < NTILES; st++) {
        const int s0 = st * STILE;
        const int validCnt = HW - s0;

        // ===== GEMM1: C1[128,64] = X * W1T; col-major A; LDG prefetch =====
        FragC c1[2];
        wmma::fill_fragment(c1[0], 0.f);
        wmma::fill_fragment(c1[1], 0.f);
        float pf[16];

        for (int ch = 0; ch < NCHUNK; ch++) {
            const int kbase = ch * KCH;
            if (ch + 1 < NCHUNK) {       // issue next chunk's LDGs first
                const int kn = (ch + 1) * KCH;
                #pragma unroll
                for (int it = 0; it < 16; it++) {
                    int idx = it * THREADS + tid;
                    int c = idx >> 7, s = idx & 127;
                    int gs = s0 + s;
                    pf[it] = (gs < HW) ? xg[(kn + c) * HW + gs] : 0.f;
                }
            }
            #pragma unroll
            for (int ks = 0; ks < 4; ks++) {
                FragAc ah, al;   // col-major: elem (m=s,k=c) at ptr[c*LDXC + s]
                wmma::load_matrix_sync(ah, sAH + (ks * 16) * LDXC + wrow, LDXC);
                wmma::load_matrix_sync(al, sAL + (ks * 16) * LDXC + wrow, LDXC);
                const int kr = kbase + ks * 16;
                #pragma unroll
                for (int j = 0; j < 2; j++) {
                    const int nt = ch2 * 2 + j;
                    FragB bh, bl;
                    wmma::load_matrix_sync(bh, sW1H + kr * LDW + nt * 16, LDW);
                    wmma::mma_sync(c1[j], ah, bh, c1[j]);
                    wmma::mma_sync(c1[j], al, bh, c1[j]);
                    wmma::load_matrix_sync(bl, sW1L + kr * LDW + nt * 16, LDW);
                    wmma::mma_sync(c1[j], ah, bl, c1[j]);
                }
            }
            if (ch + 1 < NCHUNK) {
                __syncthreads();         // all MMA reads of current chunk done
                #pragma unroll
                for (int it = 0; it < 16; it++) {
                    int idx = it * THREADS + tid;
                    int c = idx >> 7, s = idx & 127;
                    __half hi, lo; split2(pf[it], hi, lo);
                    sAH[c * LDXC + s] = hi; sAL[c * LDXC + s] = lo;
                }
                __syncthreads();
            }
        }
        __syncthreads();   // last chunk's reads done before h overwrites A
        // epilogue 1: h = relu(v+b1) -> hi/lo row-major [s][d]; zero x2
        if (tid < STILE) sX2[tid] = 0.f;
        #pragma unroll
        for (int j = 0; j < 2; j++) {
            wmma::store_matrix_sync(cw, c1[j], LDC, wmma::mem_row_major);
            __syncwarp();
            const int d = (ch2 * 2 + j) * 16 + col;
            #pragma unroll
            for (int jr = 0; jr < 8; jr++) {
                const int r = r0 + jr;
                float v = fmaxf(cw[r * LDC + col] + sB1[d], 0.f);
                __half hi, lo; split2(v, hi, lo);
                sAH[(wrow + r) * LDA + d] = hi;
                sAL[(wrow + r) * LDA + d] = lo;
            }
            __syncwarp();
        }
        __syncthreads();

        // ===== GEMM2: C2 = h * W2T (K=64); row-major A =====
        FragC c2[2];
        wmma::fill_fragment(c2[0], 0.f);
        wmma::fill_fragment(c2[1], 0.f);
        #pragma unroll
        for (int ks = 0; ks < 4; ks++) {
            FragA ah, al;
            wmma::load_matrix_sync(ah, sAH + wrow * LDA + ks * 16, LDA);
            wmma::load_matrix_sync(al, sAL + wrow * LDA + ks * 16, LDA);
            #pragma unroll
            for (int j = 0; j < 2; j++) {
                const int nt = ch2 * 2 + j;
                FragB bh, bl;
                wmma::load_matrix_sync(bh, sW2H + (ks * 16) * LDW + nt * 16, LDW);
                wmma::mma_sync(c2[j], ah, bh, c2[j]);
                wmma::mma_sync(c2[j], al, bh, c2[j]);
                wmma::load_matrix_sync(bl, sW2L + (ks * 16) * LDW + nt * 16, LDW);
                wmma::mma_sync(c2[j], ah, bl, c2[j]);
            }
        }
        __syncthreads();   // all warps done reading h before f overwrites A
        // epilogue 2: f = sigmoid(v+b2) -> A tiles; fused ||f||^2 partials
        {
            float s2r[8] = {0.f, 0.f, 0.f, 0.f, 0.f, 0.f, 0.f, 0.f};
            #pragma unroll
            for (int j = 0; j < 2; j++) {
                wmma::store_matrix_sync(cw, c2[j], LDC, wmma::mem_row_major);
                __syncwarp();
                const int d = (ch2 * 2 + j) * 16 + col;
                #pragma unroll
                for (int jr = 0; jr < 8; jr++) {
                    const int r = r0 + jr;
                    float v = cw[r * LDC + col] + sB2[d];
                    float f = 1.f / (1.f + __expf(-v));
                    s2r[jr] += f * f;
                    __half hi, lo; split2(f, hi, lo);
                    sAH[(wrow + r) * LDA + d] = hi;
                    sAL[(wrow + r) * LDA + d] = lo;
                }
                __syncwarp();
            }
            #pragma unroll
            for (int jr = 0; jr < 8; jr++) {
                s2r[jr] += __shfl_xor_sync(0xffffffffu, s2r[jr], 1);
                s2r[jr] += __shfl_xor_sync(0xffffffffu, s2r[jr], 2);
                s2r[jr] += __shfl_xor_sync(0xffffffffu, s2r[jr], 4);
                s2r[jr] += __shfl_xor_sync(0xffffffffu, s2r[jr], 8);
            }
            if ((lane & 15) == 0) {
                #pragma unroll
                for (int jr = 0; jr < 8; jr++)
                    atomicAdd(sX2 + wrow + r0 + jr, s2r[jr]);
            }
        }
        __syncthreads();

        // ---- hoist GEMM3 A fragments, then overlap next-tile X staging ----
        FragA a3h[4], a3l[4];
        #pragma unroll
        for (int ks = 0; ks < 4; ks++) {
            wmma::load_matrix_sync(a3h[ks], sAH + wrow * LDA + ks * 16, LDA);
            wmma::load_matrix_sync(a3l[ks], sAL + wrow * LDA + ks * 16, LDA);
        }
        __syncthreads();   // all hoists done before staging overwrites A
        if (st + 1 < NTILES) {
            const int ns0 = (st + 1) * STILE;
            #pragma unroll
            for (int it = 0; it < 16; it++) {
                int idx = it * THREADS + tid;
                int c = idx >> 7, s = idx & 127;
                int gs = ns0 + s;
                float v = (gs < HW) ? xg[c * HW + gs] : 0.f;
                __half hi, lo; split2(v, hi, lo);
                sAH[c * LDXC + s] = hi; sAL[c * LDXC + s] = lo;
            }
        }
        __syncthreads();   // staged chunk visible for next tile's GEMM1

        // ===== GEMM3: C3 = f * PT (K=64); register A; warp-pair splits 7/6 =====
        {
            const int ntLo = (ch2 == 0) ? 0 : 7;
            const int ntHi = (ch2 == 0) ? 7 : 13;
            for (int nt = ntLo; nt < ntHi; nt++) {
                FragC c3;
                wmma::fill_fragment(c3, 0.f);
                #pragma unroll
                for (int ks = 0; ks < 4; ks++) {
                    FragB bh, bl;
                    wmma::load_matrix_sync(bh, sPTH + (ks * 16) * LDP + nt * 16, LDP);
                    wmma::mma_sync(c3, a3h[ks], bh, c3);
                    wmma::mma_sync(c3, a3l[ks], bh, c3);
                    wmma::load_matrix_sync(bl, sPTL + (ks * 16) * LDP + nt * 16, LDP);
                    wmma::mma_sync(c3, a3h[ks], bl, c3);
                }
                wmma::store_matrix_sync(cw, c3, LDC, wmma::mem_row_major);
                __syncwarp();
                const int p = nt * 16 + col;
                const float pn2 = sP2[p];
                float mn = 3.402823466e+38f;
                #pragma unroll
                for (int jr = 0; jr < 8; jr++) {
                    const int r = r0 + jr;
                    if (wrow + r < validCnt) {
                        float v = cw[r * LDC + col];
                        mn = fminf(mn, fmaxf(sX2[wrow + r] - 2.f * v + pn2, 0.f));
                    }
                }
                mn = fminf(mn, __shfl_xor_sync(0xffffffffu, mn, 16));
                if (lane < 16 && p < PP)
                    atomicMin(sMind + p, __float_as_int(mn));
                __syncwarp();
            }
        }
        // no tile-end barrier needed: next GEMM1 reads the already-synced staged
        // chunk; sMind consumers sync below after the loop
    }
    __syncthreads();

    // ---- Outputs ----
    if (tid < PP)
        out_mind[n * PP + tid] = __int_as_float(sMind[tid]);
    for (int cls = warp; cls < NCLS; cls += NW) {   // warp per class
        float ssum = 0.f;
        for (int p = lane; p < PP; p += 32)
            ssum += __int_as_float(sMind[p]) * lastW[cls * PP + p];
        #pragma unroll
        for (int o = 16; o > 0; o >>= 1)
            ssum += __shfl_xor_sync(0xffffffffu, ssum, o);
        if (lane == 0)
            out_logits[n * NCLS + cls] = lastB[cls] - ssum;   // act = -min_dist
    }
}

extern "C" void kernel_launch(void* const* d_in, const int* in_sizes, int n_in,
                              void* d_out, int out_size) {
    (void)in_sizes; (void)n_in; (void)out_size;
    const float* x     = (const float*)d_in[0];
    const float* W1    = (const float*)d_in[1];
    const float* b1    = (const float*)d_in[2];
    const float* W2    = (const float*)d_in[3];
    const float* b2    = (const float*)d_in[4];
    const float* proto = (const float*)d_in[5];
    const float* lastW = (const float*)d_in[6];
    const float* lastB = (const float*)d_in[7];
    float* out        = (float*)d_out;
    float* out_logits = out;                 // (256,10)
    float* out_mind   = out + NB * NCLS;     // (256,200)

    cudaFuncSetAttribute(proto_h2c_kernel,
                         cudaFuncAttributeMaxDynamicSharedMemorySize, SMEM_BYTES);
    proto_h2c_kernel<<<NB, THREADS, SMEM_BYTES>>>(
        x, W1, b1, W2, b2, proto, lastW, lastB, out_logits, out_mind);
}